// round 5
// baseline (speedup 1.0000x reference)
#include <cuda_runtime.h>
#include <math.h>

#define NN   50000
#define DEG  16
#define IND  128
#define EDIM 64
#define ODIM 128
#define MT   64          // GEMM row tile
#define KC   16          // GEMM k chunk

typedef unsigned long long u64;

// ---- scratch (device globals: allocation-free rule) ----
__device__ float g_A[NN * IND];            // h @ W1 (src-side pretrans)
__device__ float g_B[NN * IND];            // h @ W2 (dst-side pretrans)
__device__ float g_agg[NN * 4 * IND];      // [mean | max | min | std] per node
__device__ float g_Wsum[4 * IND * ODIM];   // Wp1+Wp2+Wp3 folded (scalers == 1)

// ---- f32x2 helpers ----
__device__ __forceinline__ void fma2(u64 &d, u64 a, u64 b) {
    asm("fma.rn.f32x2 %0, %1, %2, %0;" : "+l"(d) : "l"(a), "l"(b));
}
__device__ __forceinline__ u64 dup2f(float x) {
    u64 r; asm("mov.b64 %0, {%1, %2};" : "=l"(r) : "f"(x), "f"(x)); return r;
}
__device__ __forceinline__ float2 unpack2(u64 v) {
    float2 r; asm("mov.b64 {%0, %1}, %2;" : "=f"(r.x), "=f"(r.y) : "l"(v)); return r;
}

// ============================================================
// K0: fold scaler blocks of W_post (amp = att = 1 since deg == 16)
// ============================================================
__global__ void k_wsum(const float* __restrict__ Wpost) {
    int i = blockIdx.x * blockDim.x + threadIdx.x;
    if (i < 4 * IND * ODIM) {
        int r = i >> 7, c = i & 127;
        g_Wsum[i] = Wpost[(IND + r) * ODIM + c]
                  + Wpost[(5 * IND + r) * ODIM + c]
                  + Wpost[(9 * IND + r) * ODIM + c];
    }
}

// ============================================================
// K1: A/B = h @ W1 / h @ W2.  grid (782, 2).  64-row tile, 4x8 thread tile.
// Double-buffered smem, inner loop pure LDS+FFMA2, 3 CTAs/SM.
// ============================================================
__global__ __launch_bounds__(256, 3) void k_ab(const float* __restrict__ h,
                                               const float* __restrict__ Wpre) {
    extern __shared__ char sm[];
    u64*   Xs = (u64*)sm;                        // [2][64][16] dup'd = 16KB
    float* Ws = (float*)(sm + 2 * MT * KC * 8);  // [2][16][128]      = 16KB

    const int m0  = blockIdx.x * MT;
    const float* Wsrc = Wpre + (size_t)blockIdx.y * IND * IND;
    float* outb = blockIdx.y ? g_B : g_A;

    const int tid = threadIdx.x;
    const int tc = tid & 15, tr = tid >> 4;
    const int r0 = tr * 4;
    const int xrow = tid >> 2, xq = tid & 3;     // X staging: 1 float4/thread

    u64 acc[4][4];
    #pragma unroll
    for (int i = 0; i < 4; i++)
        #pragma unroll
        for (int g = 0; g < 4; g++) acc[i][g] = 0ull;

    float4 px, pw[2];
    const int NCH = IND / KC;   // 8

    // prefetch + stage chunk 0
    {
        int m = m0 + xrow;
        px = make_float4(0.f, 0.f, 0.f, 0.f);
        if (m < NN) px = *(const float4*)(h + (size_t)m * IND + xq * 4);
        #pragma unroll
        for (int t = 0; t < 2; t++) {
            int it = tid + t * 256;
            int k = it >> 5, c4 = it & 31;
            pw[t] = *(const float4*)(Wsrc + (size_t)k * IND + c4 * 4);
        }
        u64* d = Xs + xrow * KC + xq * 4;
        d[0] = dup2f(px.x); d[1] = dup2f(px.y); d[2] = dup2f(px.z); d[3] = dup2f(px.w);
        #pragma unroll
        for (int t = 0; t < 2; t++) {
            int it = tid + t * 256;
            int k = it >> 5, c4 = it & 31;
            *(float4*)&Ws[k * IND + c4 * 4] = pw[t];
        }
    }
    __syncthreads();

    for (int c = 0; c < NCH; c++) {
        if (c + 1 < NCH) {
            int m = m0 + xrow;
            px = make_float4(0.f, 0.f, 0.f, 0.f);
            if (m < NN) px = *(const float4*)(h + (size_t)m * IND + (c + 1) * KC + xq * 4);
            #pragma unroll
            for (int t = 0; t < 2; t++) {
                int it = tid + t * 256;
                int k = it >> 5, c4 = it & 31;
                pw[t] = *(const float4*)(Wsrc + (size_t)((c + 1) * KC + k) * IND + c4 * 4);
            }
        }
        const u64*   Xb = Xs + (c & 1) * MT * KC;
        const float* Wb = Ws + (c & 1) * KC * IND;
        #pragma unroll
        for (int kk = 0; kk < KC; kk += 2) {
            u64 w0[4], w1[4];
            #pragma unroll
            for (int g = 0; g < 4; g++) {
                w0[g] = *(const u64*)&Wb[kk * IND + g * 32 + tc * 2];
                w1[g] = *(const u64*)&Wb[(kk + 1) * IND + g * 32 + tc * 2];
            }
            #pragma unroll
            for (int i = 0; i < 4; i++) {
                ulonglong2 xv = *(const ulonglong2*)&Xb[(r0 + i) * KC + kk];
                #pragma unroll
                for (int g = 0; g < 4; g++) {
                    fma2(acc[i][g], xv.x, w0[g]);
                    fma2(acc[i][g], xv.y, w1[g]);
                }
            }
        }
        if (c + 1 < NCH) {
            u64*   Xn = Xs + ((c + 1) & 1) * MT * KC;
            float* Wn = Ws + ((c + 1) & 1) * KC * IND;
            u64* d = Xn + xrow * KC + xq * 4;
            d[0] = dup2f(px.x); d[1] = dup2f(px.y); d[2] = dup2f(px.z); d[3] = dup2f(px.w);
            #pragma unroll
            for (int t = 0; t < 2; t++) {
                int it = tid + t * 256;
                int k = it >> 5, c4 = it & 31;
                *(float4*)&Wn[k * IND + c4 * 4] = pw[t];
            }
        }
        __syncthreads();
    }

    #pragma unroll
    for (int i = 0; i < 4; i++) {
        int m = m0 + r0 + i;
        if (m < NN) {
            float* o = outb + (size_t)m * IND;
            #pragma unroll
            for (int g = 0; g < 4; g++) {
                float2 u = unpack2(acc[i][g]);
                *(float2*)(o + g * 32 + tc * 2) = u;
            }
        }
    }
}

// ============================================================
// K2: per-node edge matvec + 4-aggregator reduce.
// 2 warps per node (8 edges each), 4 nodes per 256-thread block, 3 CTAs/SM.
// ef tile staged once per node (shared by its warp pair). Cross-warp stat
// combine through smem (ef buffer reused after matvec).
// ============================================================
__global__ __launch_bounds__(256, 3) void k_edge(const float* __restrict__ ef,
                                                 const int* __restrict__ src,
                                                 const float* __restrict__ Wpre,
                                                 const float* __restrict__ bpre) {
    extern __shared__ char smem2[];
    float* W3s = (float*)smem2;                                  // [64][128] = 32KB
    u64*   ef2 = (u64*)(smem2 + EDIM * IND * sizeof(float));     // [4][16][64] dup = 32KB

    const int tid  = threadIdx.x;
    const int warp = tid >> 5, lane = tid & 31;
    const int nl   = warp >> 1;            // node within block (0..3)
    const int eh   = warp & 1;             // edge half (0: edges 0-7, 1: 8-15)
    const int n    = blockIdx.x * 4 + nl;

    // stage W3 (Wpre rows 256..319) via float4
    for (int i = tid; i < EDIM * IND / 4; i += 256)
        ((float4*)W3s)[i] = ((const float4*)(Wpre + 2 * IND * IND))[i];

    // stage 4 nodes' ef (contiguous: node n owns rows 16n..16n+15) duplicated
    const float* efb = ef + (size_t)blockIdx.x * 4 * DEG * EDIM;
    for (int i = tid; i < 4 * DEG * EDIM / 4; i += 256) {
        float4 v = ((const float4*)efb)[i];
        u64* d = ef2 + i * 4;
        d[0] = dup2f(v.x); d[1] = dup2f(v.y); d[2] = dup2f(v.z); d[3] = dup2f(v.w);
    }
    __syncthreads();

    const int c0 = 2 * lane, c1 = 64 + 2 * lane;
    const u64* myef = ef2 + nl * (DEG * EDIM) + eh * 8 * EDIM;

    u64 acc[8][2];
    #pragma unroll
    for (int j = 0; j < 8; j++) { acc[j][0] = 0ull; acc[j][1] = 0ull; }

    for (int kc = 0; kc < EDIM; kc += 4) {
        u64 w0[4], w1[4];
        #pragma unroll
        for (int q = 0; q < 4; q++) {
            w0[q] = *(const u64*)&W3s[(kc + q) * IND + c0];
            w1[q] = *(const u64*)&W3s[(kc + q) * IND + c1];
        }
        #pragma unroll
        for (int j = 0; j < 8; j++) {
            const u64* ap = myef + j * EDIM + kc;
            ulonglong2 a01 = *(const ulonglong2*)(ap);
            ulonglong2 a23 = *(const ulonglong2*)(ap + 2);
            fma2(acc[j][0], a01.x, w0[0]); fma2(acc[j][1], a01.x, w1[0]);
            fma2(acc[j][0], a01.y, w0[1]); fma2(acc[j][1], a01.y, w1[1]);
            fma2(acc[j][0], a23.x, w0[2]); fma2(acc[j][1], a23.x, w1[2]);
            fma2(acc[j][0], a23.y, w0[3]); fma2(acc[j][1], a23.y, w1[3]);
        }
    }

    // epilogue: e_j = acc_j + A[src_j] + B[n] + b_pre; partial stats over 8 edges
    int sreg[8];
    const int* srcp = src + n * DEG + eh * 8;
    #pragma unroll
    for (int j = 0; j < 8; j++) sreg[j] = srcp[j];

    float2 B0 = *(const float2*)&g_B[(size_t)n * IND + c0];
    float2 B1 = *(const float2*)&g_B[(size_t)n * IND + c1];
    {
        float2 bp0 = *(const float2*)&bpre[c0];
        float2 bp1 = *(const float2*)&bpre[c1];
        B0.x += bp0.x; B0.y += bp0.y; B1.x += bp1.x; B1.y += bp1.y;
    }

    float2 s1a = {0.f, 0.f}, s2a = {0.f, 0.f};
    float2 s1b = {0.f, 0.f}, s2b = {0.f, 0.f};
    float2 mxa = {-3.402823466e38f, -3.402823466e38f}, mna = {3.402823466e38f, 3.402823466e38f};
    float2 mxb = mxa, mnb = mna;

    #pragma unroll
    for (int j = 0; j < 8; j++) {
        const float* Ar = g_A + (size_t)sreg[j] * IND;
        float2 a0 = *(const float2*)&Ar[c0];
        float2 a1 = *(const float2*)&Ar[c1];
        float2 e0 = unpack2(acc[j][0]);
        float2 e1 = unpack2(acc[j][1]);
        e0.x += a0.x + B0.x; e0.y += a0.y + B0.y;
        e1.x += a1.x + B1.x; e1.y += a1.y + B1.y;
        s1a.x += e0.x; s1a.y += e0.y; s1b.x += e1.x; s1b.y += e1.y;
        s2a.x += e0.x * e0.x; s2a.y += e0.y * e0.y;
        s2b.x += e1.x * e1.x; s2b.y += e1.y * e1.y;
        mxa.x = fmaxf(mxa.x, e0.x); mxa.y = fmaxf(mxa.y, e0.y);
        mxb.x = fmaxf(mxb.x, e1.x); mxb.y = fmaxf(mxb.y, e1.y);
        mna.x = fminf(mna.x, e0.x); mna.y = fminf(mna.y, e0.y);
        mnb.x = fminf(mnb.x, e1.x); mnb.y = fminf(mnb.y, e1.y);
    }

    // cross-warp combine: eh==1 publishes partials (ef2 reused), eh==0 finishes
    float* part = (float*)ef2;   // [4 nodes][8 stats][64 floats] = 8KB
    __syncthreads();             // all warps done reading ef2
    if (eh == 1) {
        float* p = part + nl * 512 + 2 * lane;
        *(float2*)(p + 0 * 64) = s1a; *(float2*)(p + 1 * 64) = s1b;
        *(float2*)(p + 2 * 64) = s2a; *(float2*)(p + 3 * 64) = s2b;
        *(float2*)(p + 4 * 64) = mxa; *(float2*)(p + 5 * 64) = mxb;
        *(float2*)(p + 6 * 64) = mna; *(float2*)(p + 7 * 64) = mnb;
    }
    __syncthreads();
    if (eh == 0) {
        const float* p = part + nl * 512 + 2 * lane;
        float2 t;
        t = *(const float2*)(p + 0 * 64); s1a.x += t.x; s1a.y += t.y;
        t = *(const float2*)(p + 1 * 64); s1b.x += t.x; s1b.y += t.y;
        t = *(const float2*)(p + 2 * 64); s2a.x += t.x; s2a.y += t.y;
        t = *(const float2*)(p + 3 * 64); s2b.x += t.x; s2b.y += t.y;
        t = *(const float2*)(p + 4 * 64); mxa.x = fmaxf(mxa.x, t.x); mxa.y = fmaxf(mxa.y, t.y);
        t = *(const float2*)(p + 5 * 64); mxb.x = fmaxf(mxb.x, t.x); mxb.y = fmaxf(mxb.y, t.y);
        t = *(const float2*)(p + 6 * 64); mna.x = fminf(mna.x, t.x); mna.y = fminf(mna.y, t.y);
        t = *(const float2*)(p + 7 * 64); mnb.x = fminf(mnb.x, t.x); mnb.y = fminf(mnb.y, t.y);

        const float inv = 1.0f / (float)DEG;
        float2 mea = {s1a.x * inv, s1a.y * inv};
        float2 meb = {s1b.x * inv, s1b.y * inv};
        float2 sda, sdb;
        sda.x = sqrtf(fmaxf(s2a.x * inv - mea.x * mea.x, 0.f) + 1e-5f);
        sda.y = sqrtf(fmaxf(s2a.y * inv - mea.y * mea.y, 0.f) + 1e-5f);
        sdb.x = sqrtf(fmaxf(s2b.x * inv - meb.x * meb.x, 0.f) + 1e-5f);
        sdb.y = sqrtf(fmaxf(s2b.y * inv - meb.y * meb.y, 0.f) + 1e-5f);

        float* aggp = g_agg + (size_t)n * (4 * IND);
        *(float2*)&aggp[c0]           = mea; *(float2*)&aggp[c1]           = meb;
        *(float2*)&aggp[IND + c0]     = mxa; *(float2*)&aggp[IND + c1]     = mxb;
        *(float2*)&aggp[2 * IND + c0] = mna; *(float2*)&aggp[2 * IND + c1] = mnb;
        *(float2*)&aggp[3 * IND + c0] = sda; *(float2*)&aggp[3 * IND + c1] = sdb;
    }
}

// ============================================================
// K3: out = [h | agg] @ [Wp0 ; Wsum] + b_post.  K=640, 40 chunks of 16.
// Same GEMM structure as k_ab (64-row tile, 4x8 thread tile, 3 CTAs/SM).
// ============================================================
__global__ __launch_bounds__(256, 3) void k_post(const float* __restrict__ h,
                                                 const float* __restrict__ Wpost,
                                                 const float* __restrict__ bpost,
                                                 float* __restrict__ out) {
    extern __shared__ char sm[];
    u64*   Xs = (u64*)sm;                        // [2][64][16]
    float* Ws = (float*)(sm + 2 * MT * KC * 8);  // [2][16][128]

    const int m0  = blockIdx.x * MT;
    const int tid = threadIdx.x;
    const int tc = tid & 15, tr = tid >> 4;
    const int r0 = tr * 4;
    const int xrow = tid >> 2, xq = tid & 3;

    u64 acc[4][4];
    #pragma unroll
    for (int i = 0; i < 4; i++)
        #pragma unroll
        for (int g = 0; g < 4; g++) acc[i][g] = 0ull;

    float4 px, pw[2];
    const int NCH = 40;

    {
        int m = m0 + xrow;
        px = make_float4(0.f, 0.f, 0.f, 0.f);
        if (m < NN) px = *(const float4*)(h + (size_t)m * IND + xq * 4);
        #pragma unroll
        for (int t = 0; t < 2; t++) {
            int it = tid + t * 256;
            int k = it >> 5, c4 = it & 31;
            pw[t] = *(const float4*)(Wpost + (size_t)k * ODIM + c4 * 4);
        }
        u64* d = Xs + xrow * KC + xq * 4;
        d[0] = dup2f(px.x); d[1] = dup2f(px.y); d[2] = dup2f(px.z); d[3] = dup2f(px.w);
        #pragma unroll
        for (int t = 0; t < 2; t++) {
            int it = tid + t * 256;
            int k = it >> 5, c4 = it & 31;
            *(float4*)&Ws[k * ODIM + c4 * 4] = pw[t];
        }
    }
    __syncthreads();

    for (int c = 0; c < NCH; c++) {
        if (c + 1 < NCH) {
            int cn = c + 1;
            int m = m0 + xrow;
            px = make_float4(0.f, 0.f, 0.f, 0.f);
            if (m < NN) {
                const float* p = (cn < 8)
                    ? (h + (size_t)m * IND + cn * KC + xq * 4)
                    : (g_agg + (size_t)m * 4 * IND + (cn - 8) * KC + xq * 4);
                px = *(const float4*)p;
            }
            #pragma unroll
            for (int t = 0; t < 2; t++) {
                int it = tid + t * 256;
                int k = it >> 5, c4 = it & 31;
                const float* wp = (cn < 8)
                    ? (Wpost + (size_t)(cn * KC + k) * ODIM + c4 * 4)
                    : (g_Wsum + (size_t)((cn - 8) * KC + k) * ODIM + c4 * 4);
                pw[t] = *(const float4*)wp;
            }
        }
        const u64*   Xb = Xs + (c & 1) * MT * KC;
        const float* Wb = Ws + (c & 1) * KC * ODIM;
        #pragma unroll
        for (int kk = 0; kk < KC; kk += 2) {
            u64 w0[4], w1[4];
            #pragma unroll
            for (int g = 0; g < 4; g++) {
                w0[g] = *(const u64*)&Wb[kk * ODIM + g * 32 + tc * 2];
                w1[g] = *(const u64*)&Wb[(kk + 1) * ODIM + g * 32 + tc * 2];
            }
            #pragma unroll
            for (int i = 0; i < 4; i++) {
                ulonglong2 xv = *(const ulonglong2*)&Xb[(r0 + i) * KC + kk];
                #pragma unroll
                for (int g = 0; g < 4; g++) {
                    fma2(acc[i][g], xv.x, w0[g]);
                    fma2(acc[i][g], xv.y, w1[g]);
                }
            }
        }
        if (c + 1 < NCH) {
            u64*   Xn = Xs + ((c + 1) & 1) * MT * KC;
            float* Wn = Ws + ((c + 1) & 1) * KC * ODIM;
            u64* d = Xn + xrow * KC + xq * 4;
            d[0] = dup2f(px.x); d[1] = dup2f(px.y); d[2] = dup2f(px.z); d[3] = dup2f(px.w);
            #pragma unroll
            for (int t = 0; t < 2; t++) {
                int it = tid + t * 256;
                int k = it >> 5, c4 = it & 31;
                *(float4*)&Wn[k * ODIM + c4 * 4] = pw[t];
            }
        }
        __syncthreads();
    }

    #pragma unroll
    for (int i = 0; i < 4; i++) {
        int m = m0 + r0 + i;
        if (m < NN) {
            float* o = out + (size_t)m * ODIM;
            #pragma unroll
            for (int g = 0; g < 4; g++) {
                float2 b = *(const float2*)&bpost[g * 32 + tc * 2];
                float2 u = unpack2(acc[i][g]);
                u.x += b.x; u.y += b.y;
                *(float2*)(o + g * 32 + tc * 2) = u;
            }
        }
    }
}

// ============================================================
extern "C" void kernel_launch(void* const* d_in, const int* in_sizes, int n_in,
                              void* d_out, int out_size) {
    const float* h     = (const float*)d_in[0];
    const float* ef    = (const float*)d_in[1];
    const int*   src   = (const int*)d_in[2];
    // d_in[3] = dst: implicit (dst[e] = e/16), unused
    const float* Wpre  = (const float*)d_in[4];
    const float* bpre  = (const float*)d_in[5];
    const float* Wpost = (const float*)d_in[6];
    const float* bpost = (const float*)d_in[7];
    float* out = (float*)d_out;

    const int smem_gemm = 2 * MT * KC * 8 + 2 * KC * 128 * 4;               // 32768
    const int smem_edge = EDIM * IND * sizeof(float) + 4 * DEG * EDIM * 8;  // 65536

    static bool attr_done = false;
    if (!attr_done) {
        cudaFuncSetAttribute(k_ab,   cudaFuncAttributeMaxDynamicSharedMemorySize, smem_gemm);
        cudaFuncSetAttribute(k_edge, cudaFuncAttributeMaxDynamicSharedMemorySize, smem_edge);
        cudaFuncSetAttribute(k_post, cudaFuncAttributeMaxDynamicSharedMemorySize, smem_gemm);
        attr_done = true;
    }

    const int mblocks = (NN + MT - 1) / MT;   // 782
    k_wsum<<<(4 * IND * ODIM + 255) / 256, 256>>>(Wpost);
    dim3 gab(mblocks, 2);
    k_ab  <<<gab, 256, smem_gemm>>>(h, Wpre);
    k_edge<<<NN / 4, 256, smem_edge>>>(ef, src, Wpre, bpre);
    k_post<<<mblocks, 256, smem_gemm>>>(h, Wpost, bpost, out);
}

// round 8
// speedup vs baseline: 1.3663x; 1.3663x over previous
#include <cuda_runtime.h>
#include <math.h>
#include <stdint.h>

#define NN   50000
#define DEG  16
#define IND  128
#define EDIM 64
#define ODIM 128

typedef unsigned long long u64;

// ---- scratch (device globals: allocation-free rule) ----
__device__ float g_A[NN * IND];             // h @ W1
__device__ float g_B[NN * IND];             // h @ W2
__device__ float g_agg[NN * 4 * IND];       // [mean|max|min|std]
// transposed + tf32-split weights (built once per launch by k_wprep)
__device__ float g_WT1h[IND * IND],  g_WT1l[IND * IND];   // [n][k]
__device__ float g_WT2h[IND * IND],  g_WT2l[IND * IND];
__device__ float g_WT3h[IND * EDIM], g_WT3l[IND * EDIM];  // edge W3^T [n][k], k<64
__device__ float g_WTph[IND * 640],  g_WTpl[IND * 640];   // [n][k] k<128: Wp0; else folded Wsum

// ---- helpers ----
__device__ __forceinline__ float tf32r(float x) {
    uint32_t u; asm("cvt.rna.tf32.f32 %0, %1;" : "=r"(u) : "f"(x));
    return __uint_as_float(u);
}
__device__ __forceinline__ void mma8(float* c, uint32_t a0, uint32_t a1, uint32_t a2, uint32_t a3,
                                     uint32_t b0, uint32_t b1) {
    asm volatile(
        "mma.sync.aligned.m16n8k8.row.col.f32.tf32.tf32.f32 "
        "{%0,%1,%2,%3}, {%4,%5,%6,%7}, {%8,%9}, {%0,%1,%2,%3};"
        : "+f"(c[0]), "+f"(c[1]), "+f"(c[2]), "+f"(c[3])
        : "r"(a0), "r"(a1), "r"(a2), "r"(a3), "r"(b0), "r"(b1));
}

#define AS_STRIDE 36           // 32 k + 4 pad (floats); row = 144B, float4-aligned, conflict-free frags
#define SM_AH 0
#define SM_AL 18432
#define SM_BH 36864
#define SM_BL 55296
#define SM_GEMM_TOT 73728

// ============================================================
// K0: build transposed tf32-split weights; fold Wsum (deg == 16 -> scalers == 1)
// ============================================================
__global__ void k_wprep(const float* __restrict__ Wpre, const float* __restrict__ Wpost) {
    int i = blockIdx.x * blockDim.x + threadIdx.x;
    if (i < IND * IND) {
        int n = i >> 7, k = i & 127;
        float w1 = Wpre[k * IND + n];
        float w2 = Wpre[IND * IND + k * IND + n];
        float h1 = tf32r(w1), h2 = tf32r(w2);
        g_WT1h[n * IND + k] = h1; g_WT1l[n * IND + k] = tf32r(w1 - h1);
        g_WT2h[n * IND + k] = h2; g_WT2l[n * IND + k] = tf32r(w2 - h2);
    }
    if (i < IND * EDIM) {
        int n = i & 127, k = i >> 7;   // k < 64
        float w3 = Wpre[2 * IND * IND + k * IND + n];
        float h3 = tf32r(w3);
        g_WT3h[n * EDIM + k] = h3; g_WT3l[n * EDIM + k] = tf32r(w3 - h3);
    }
    if (i < IND * 640) {
        int n = i / 640, k = i % 640;
        float w;
        if (k < IND) w = Wpost[k * ODIM + n];
        else {
            int r = k - IND;
            w = Wpost[(IND + r) * ODIM + n] + Wpost[(5 * IND + r) * ODIM + n]
              + Wpost[(9 * IND + r) * ODIM + n];
        }
        float hh = tf32r(w);
        g_WTph[(size_t)n * 640 + k] = hh;
        g_WTpl[(size_t)n * 640 + k] = tf32r(w - hh);
    }
}

// ============================================================
// K1/K3: warp-mma tf32 GEMM (3xTF32 split). 128x128 CTA tile, K chunks of 32.
// 8 warps = 4(m) x 2(n); each warp 32x64 via 2x8 m16n8k8 frags.
// sel: 0 -> g_A = h@W1; 1 -> g_B = h@W2; 2 -> out = [h|agg]@WTp^T + bias;
// sel 3: AB-combined (blockIdx.y picks 0/1).
// ============================================================
__global__ __launch_bounds__(256, 2) void k_gemm_mma(const float* __restrict__ X0,
                                                     const float* __restrict__ bias_in,
                                                     float* __restrict__ out_in,
                                                     int sel) {
    extern __shared__ float sm[];
    float* Ash = sm + SM_AH / 4;
    float* Asl = sm + SM_AL / 4;
    float* Bsh = sm + SM_BH / 4;
    float* Bsl = sm + SM_BL / 4;

    if (sel == 3) sel = blockIdx.y;

    const float *BTh, *BTl, *bias = nullptr;
    float* outp;
    int Ktot;
    if (sel == 0)      { BTh = g_WT1h; BTl = g_WT1l; outp = g_A;    Ktot = 128; }
    else if (sel == 1) { BTh = g_WT2h; BTl = g_WT2l; outp = g_B;    Ktot = 128; }
    else               { BTh = g_WTph; BTl = g_WTpl; outp = out_in; Ktot = 640; bias = bias_in; }
    const int NCH = Ktot / 32;

    const int tid = threadIdx.x;
    const int wid = tid >> 5, lane = tid & 31;
    const int g = lane >> 2, t4 = lane & 3;
    const int warp_m = wid & 3, warp_n = wid >> 2;
    const int m0 = blockIdx.x * 128;

    float acc[2][8][4];
    #pragma unroll
    for (int mt = 0; mt < 2; mt++)
        #pragma unroll
        for (int nt = 0; nt < 8; nt++)
            #pragma unroll
            for (int q = 0; q < 4; q++) acc[mt][nt][q] = 0.f;

    for (int c = 0; c < NCH; c++) {
        // ---- stage A rows (tf32 hi/lo split on the fly) ----
        #pragma unroll
        for (int t = 0; t < 4; t++) {
            int it = tid + t * 256;              // 1024 float4s
            int row = it >> 3, q = it & 7;
            int m = m0 + row;
            float4 v = make_float4(0.f, 0.f, 0.f, 0.f);
            if (m < NN) {
                const float* p = (sel != 2) ? (X0 + (size_t)m * IND + c * 32 + q * 4)
                    : ((c < 4) ? (X0 + (size_t)m * IND + c * 32 + q * 4)
                               : (g_agg + (size_t)m * 4 * IND + (c - 4) * 32 + q * 4));
                v = *(const float4*)p;
            }
            float4 hi, lo;
            hi.x = tf32r(v.x); hi.y = tf32r(v.y); hi.z = tf32r(v.z); hi.w = tf32r(v.w);
            lo.x = tf32r(v.x - hi.x); lo.y = tf32r(v.y - hi.y);
            lo.z = tf32r(v.z - hi.z); lo.w = tf32r(v.w - hi.w);
            *(float4*)&Ash[row * AS_STRIDE + q * 4] = hi;
            *(float4*)&Asl[row * AS_STRIDE + q * 4] = lo;
        }
        // ---- stage B (pre-split, [n][k]) ----
        #pragma unroll
        for (int t = 0; t < 4; t++) {
            int it = tid + t * 256;
            int n = it >> 3, q = it & 7;
            *(float4*)&Bsh[n * AS_STRIDE + q * 4] = *(const float4*)(BTh + (size_t)n * Ktot + c * 32 + q * 4);
            *(float4*)&Bsl[n * AS_STRIDE + q * 4] = *(const float4*)(BTl + (size_t)n * Ktot + c * 32 + q * 4);
        }
        __syncthreads();

        #pragma unroll
        for (int k0 = 0; k0 < 32; k0 += 8) {
            uint32_t ah[2][4], al[2][4];
            #pragma unroll
            for (int mt = 0; mt < 2; mt++) {
                int r0 = warp_m * 32 + mt * 16 + g;
                ah[mt][0] = __float_as_uint(Ash[r0 * AS_STRIDE + k0 + t4]);
                ah[mt][1] = __float_as_uint(Ash[(r0 + 8) * AS_STRIDE + k0 + t4]);
                ah[mt][2] = __float_as_uint(Ash[r0 * AS_STRIDE + k0 + t4 + 4]);
                ah[mt][3] = __float_as_uint(Ash[(r0 + 8) * AS_STRIDE + k0 + t4 + 4]);
                al[mt][0] = __float_as_uint(Asl[r0 * AS_STRIDE + k0 + t4]);
                al[mt][1] = __float_as_uint(Asl[(r0 + 8) * AS_STRIDE + k0 + t4]);
                al[mt][2] = __float_as_uint(Asl[r0 * AS_STRIDE + k0 + t4 + 4]);
                al[mt][3] = __float_as_uint(Asl[(r0 + 8) * AS_STRIDE + k0 + t4 + 4]);
            }
            #pragma unroll
            for (int nt = 0; nt < 8; nt++) {
                int n = warp_n * 64 + nt * 8 + g;
                uint32_t bh0 = __float_as_uint(Bsh[n * AS_STRIDE + k0 + t4]);
                uint32_t bh1 = __float_as_uint(Bsh[n * AS_STRIDE + k0 + t4 + 4]);
                uint32_t bl0 = __float_as_uint(Bsl[n * AS_STRIDE + k0 + t4]);
                uint32_t bl1 = __float_as_uint(Bsl[n * AS_STRIDE + k0 + t4 + 4]);
                #pragma unroll
                for (int mt = 0; mt < 2; mt++) {
                    mma8(acc[mt][nt], ah[mt][0], ah[mt][1], ah[mt][2], ah[mt][3], bh0, bh1);
                    mma8(acc[mt][nt], al[mt][0], al[mt][1], al[mt][2], al[mt][3], bh0, bh1);
                    mma8(acc[mt][nt], ah[mt][0], ah[mt][1], ah[mt][2], ah[mt][3], bl0, bl1);
                }
            }
        }
        __syncthreads();
    }

    // ---- epilogue ----
    #pragma unroll
    for (int mt = 0; mt < 2; mt++) {
        int r0 = m0 + warp_m * 32 + mt * 16 + g;
        #pragma unroll
        for (int nt = 0; nt < 8; nt++) {
            int col = warp_n * 64 + nt * 8 + t4 * 2;
            float b0 = 0.f, b1 = 0.f;
            if (bias) { b0 = bias[col]; b1 = bias[col + 1]; }
            if (r0 < NN) {
                float2 u = {acc[mt][nt][0] + b0, acc[mt][nt][1] + b1};
                *(float2*)(outp + (size_t)r0 * 128 + col) = u;
            }
            if (r0 + 8 < NN) {
                float2 u = {acc[mt][nt][2] + b0, acc[mt][nt][3] + b1};
                *(float2*)(outp + (size_t)(r0 + 8) * 128 + col) = u;
            }
        }
    }
}

// ============================================================
// K2: edge GEMM (ef@W3, tf32 3-split) fused with 4-aggregator reduce.
// CTA tile = 128 edges = EXACTLY 8 nodes (dst = e/16). K=64 in 2 chunks.
// Phase 1: warp-mma -> e tile in smem. Phase 2: warp w reduces node w
// (16 rows), adding A[src]+B[n]+b_pre during the read.
// ============================================================
#define ES_STRIDE 132
__global__ __launch_bounds__(256, 2) void k_edge_mma(const float* __restrict__ ef,
                                                     const int* __restrict__ src,
                                                     const float* __restrict__ bpre) {
    extern __shared__ float sm[];
    float* Ash = sm + SM_AH / 4;
    float* Asl = sm + SM_AL / 4;
    float* Bsh = sm + SM_BH / 4;
    float* Bsl = sm + SM_BL / 4;
    float* Es  = sm;                       // overlays A/B after mma phase: [128][132]

    const int tid = threadIdx.x;
    const int wid = tid >> 5, lane = tid & 31;
    const int g = lane >> 2, t4 = lane & 3;
    const int warp_m = wid & 3, warp_n = wid >> 2;
    const size_t m0 = (size_t)blockIdx.x * 128;     // edge row base (always full tile)

    float acc[2][8][4];
    #pragma unroll
    for (int mt = 0; mt < 2; mt++)
        #pragma unroll
        for (int nt = 0; nt < 8; nt++)
            #pragma unroll
            for (int q = 0; q < 4; q++) acc[mt][nt][q] = 0.f;

    #pragma unroll
    for (int c = 0; c < 2; c++) {
        #pragma unroll
        for (int t = 0; t < 4; t++) {
            int it = tid + t * 256;
            int row = it >> 3, q = it & 7;
            float4 v = *(const float4*)(ef + (m0 + row) * EDIM + c * 32 + q * 4);
            float4 hi, lo;
            hi.x = tf32r(v.x); hi.y = tf32r(v.y); hi.z = tf32r(v.z); hi.w = tf32r(v.w);
            lo.x = tf32r(v.x - hi.x); lo.y = tf32r(v.y - hi.y);
            lo.z = tf32r(v.z - hi.z); lo.w = tf32r(v.w - hi.w);
            *(float4*)&Ash[row * AS_STRIDE + q * 4] = hi;
            *(float4*)&Asl[row * AS_STRIDE + q * 4] = lo;
        }
        #pragma unroll
        for (int t = 0; t < 4; t++) {
            int it = tid + t * 256;
            int n = it >> 3, q = it & 7;
            *(float4*)&Bsh[n * AS_STRIDE + q * 4] = *(const float4*)(g_WT3h + (size_t)n * EDIM + c * 32 + q * 4);
            *(float4*)&Bsl[n * AS_STRIDE + q * 4] = *(const float4*)(g_WT3l + (size_t)n * EDIM + c * 32 + q * 4);
        }
        __syncthreads();

        #pragma unroll
        for (int k0 = 0; k0 < 32; k0 += 8) {
            uint32_t ah[2][4], al[2][4];
            #pragma unroll
            for (int mt = 0; mt < 2; mt++) {
                int r0 = warp_m * 32 + mt * 16 + g;
                ah[mt][0] = __float_as_uint(Ash[r0 * AS_STRIDE + k0 + t4]);
                ah[mt][1] = __float_as_uint(Ash[(r0 + 8) * AS_STRIDE + k0 + t4]);
                ah[mt][2] = __float_as_uint(Ash[r0 * AS_STRIDE + k0 + t4 + 4]);
                ah[mt][3] = __float_as_uint(Ash[(r0 + 8) * AS_STRIDE + k0 + t4 + 4]);
                al[mt][0] = __float_as_uint(Asl[r0 * AS_STRIDE + k0 + t4]);
                al[mt][1] = __float_as_uint(Asl[(r0 + 8) * AS_STRIDE + k0 + t4]);
                al[mt][2] = __float_as_uint(Asl[r0 * AS_STRIDE + k0 + t4 + 4]);
                al[mt][3] = __float_as_uint(Asl[(r0 + 8) * AS_STRIDE + k0 + t4 + 4]);
            }
            #pragma unroll
            for (int nt = 0; nt < 8; nt++) {
                int n = warp_n * 64 + nt * 8 + g;
                uint32_t bh0 = __float_as_uint(Bsh[n * AS_STRIDE + k0 + t4]);
                uint32_t bh1 = __float_as_uint(Bsh[n * AS_STRIDE + k0 + t4 + 4]);
                uint32_t bl0 = __float_as_uint(Bsl[n * AS_STRIDE + k0 + t4]);
                uint32_t bl1 = __float_as_uint(Bsl[n * AS_STRIDE + k0 + t4 + 4]);
                #pragma unroll
                for (int mt = 0; mt < 2; mt++) {
                    mma8(acc[mt][nt], ah[mt][0], ah[mt][1], ah[mt][2], ah[mt][3], bh0, bh1);
                    mma8(acc[mt][nt], al[mt][0], al[mt][1], al[mt][2], al[mt][3], bh0, bh1);
                    mma8(acc[mt][nt], ah[mt][0], ah[mt][1], ah[mt][2], ah[mt][3], bl0, bl1);
                }
            }
        }
        __syncthreads();
    }

    // ---- spill e tile to smem (overlays A/B buffers) ----
    #pragma unroll
    for (int mt = 0; mt < 2; mt++) {
        int r0 = warp_m * 32 + mt * 16 + g;
        #pragma unroll
        for (int nt = 0; nt < 8; nt++) {
            int col = warp_n * 64 + nt * 8 + t4 * 2;
            *(float2*)&Es[r0 * ES_STRIDE + col]       = *(float2*)&acc[mt][nt][0];
            *(float2*)&Es[(r0 + 8) * ES_STRIDE + col] = *(float2*)&acc[mt][nt][2];
        }
    }
    __syncthreads();

    // ---- phase 2: warp w reduces node (blockIdx.x*8 + w); lane owns 4 cols ----
    {
        const int n = blockIdx.x * 8 + wid;
        const int c0 = lane * 4;
        float4 Bb = *(const float4*)&g_B[(size_t)n * IND + c0];
        float4 bp = *(const float4*)&bpre[c0];
        Bb.x += bp.x; Bb.y += bp.y; Bb.z += bp.z; Bb.w += bp.w;

        int sreg[DEG];
        const int* srcp = src + n * DEG;
        #pragma unroll
        for (int j = 0; j < DEG; j++) sreg[j] = srcp[j];

        float4 s1 = {0.f, 0.f, 0.f, 0.f}, s2 = {0.f, 0.f, 0.f, 0.f};
        float4 mx = {-3.4e38f, -3.4e38f, -3.4e38f, -3.4e38f};
        float4 mn = {3.4e38f, 3.4e38f, 3.4e38f, 3.4e38f};

        #pragma unroll
        for (int j = 0; j < DEG; j++) {
            float4 ev = *(const float4*)&Es[(wid * 16 + j) * ES_STRIDE + c0];
            float4 av = *(const float4*)&g_A[(size_t)sreg[j] * IND + c0];
            float4 e;
            e.x = ev.x + av.x + Bb.x; e.y = ev.y + av.y + Bb.y;
            e.z = ev.z + av.z + Bb.z; e.w = ev.w + av.w + Bb.w;
            s1.x += e.x; s1.y += e.y; s1.z += e.z; s1.w += e.w;
            s2.x += e.x * e.x; s2.y += e.y * e.y; s2.z += e.z * e.z; s2.w += e.w * e.w;
            mx.x = fmaxf(mx.x, e.x); mx.y = fmaxf(mx.y, e.y);
            mx.z = fmaxf(mx.z, e.z); mx.w = fmaxf(mx.w, e.w);
            mn.x = fminf(mn.x, e.x); mn.y = fminf(mn.y, e.y);
            mn.z = fminf(mn.z, e.z); mn.w = fminf(mn.w, e.w);
        }

        const float inv = 1.0f / (float)DEG;
        float4 me = {s1.x * inv, s1.y * inv, s1.z * inv, s1.w * inv};
        float4 sd;
        sd.x = sqrtf(fmaxf(s2.x * inv - me.x * me.x, 0.f) + 1e-5f);
        sd.y = sqrtf(fmaxf(s2.y * inv - me.y * me.y, 0.f) + 1e-5f);
        sd.z = sqrtf(fmaxf(s2.z * inv - me.z * me.z, 0.f) + 1e-5f);
        sd.w = sqrtf(fmaxf(s2.w * inv - me.w * me.w, 0.f) + 1e-5f);

        float* aggp = g_agg + (size_t)n * (4 * IND);
        *(float4*)&aggp[c0]            = me;
        *(float4*)&aggp[IND + c0]      = mx;
        *(float4*)&aggp[2 * IND + c0]  = mn;
        *(float4*)&aggp[3 * IND + c0]  = sd;
    }
}

// ============================================================
extern "C" void kernel_launch(void* const* d_in, const int* in_sizes, int n_in,
                              void* d_out, int out_size) {
    const float* h     = (const float*)d_in[0];
    const float* ef    = (const float*)d_in[1];
    const int*   src   = (const int*)d_in[2];
    // d_in[3] = dst: implicit (dst[e] = e/16), unused
    const float* Wpre  = (const float*)d_in[4];
    const float* bpre  = (const float*)d_in[5];
    const float* Wpost = (const float*)d_in[6];
    const float* bpost = (const float*)d_in[7];
    float* out = (float*)d_out;

    static bool attr_done = false;
    if (!attr_done) {
        cudaFuncSetAttribute(k_gemm_mma, cudaFuncAttributeMaxDynamicSharedMemorySize, SM_GEMM_TOT);
        cudaFuncSetAttribute(k_edge_mma, cudaFuncAttributeMaxDynamicSharedMemorySize, SM_GEMM_TOT);
        attr_done = true;
    }

    const int mblocks = (NN + 127) / 128;   // 391
    k_wprep<<<(IND * 640 + 255) / 256, 256>>>(Wpre, Wpost);
    dim3 gab(mblocks, 2);
    k_gemm_mma<<<gab, 256, SM_GEMM_TOT>>>(h, nullptr, nullptr, 3);     // g_A, g_B
    k_edge_mma<<<NN * DEG / 128, 256, SM_GEMM_TOT>>>(ef, src, bpre);   // g_agg
    k_gemm_mma<<<mblocks, 256, SM_GEMM_TOT>>>(h, bpost, out, 2);       // out
}